// round 1
// baseline (speedup 1.0000x reference)
#include <cuda_runtime.h>
#include <cuda_bf16.h>
#include <cstdint>

// Problem constants (GCL_GCN: N=50000, E=800000, FEAT=128, HID1=128, HID2=64)
#define N_MAX   50000
#define FEAT    128
#define HID1    128
#define HID2    64

// ---------------- scratch (static device globals; no allocation) -------------
__device__ float g_h1  [(size_t)N_MAX * HID1];   // X @ W1
__device__ float g_agg1[(size_t)N_MAX * HID1];   // aggregated layer1 (then relu'd feats)
__device__ float g_h2  [(size_t)N_MAX * HID2];   // relu(agg1) @ W2
__device__ int   g_deg [N_MAX];
__device__ float g_dinv[N_MAX];

// ---------------- tiny utility kernels ---------------------------------------
__global__ void zero_f4_kernel(float4* __restrict__ p, int n4) {
    int i = blockIdx.x * blockDim.x + threadIdx.x;
    if (i < n4) p[i] = make_float4(0.f, 0.f, 0.f, 0.f);
}

__global__ void zero_i_kernel(int* __restrict__ p, int n) {
    int i = blockIdx.x * blockDim.x + threadIdx.x;
    if (i < n) p[i] = 0;
}

__global__ void count_deg_kernel(const int* __restrict__ dst, int* __restrict__ deg, int E) {
    int e = blockIdx.x * blockDim.x + threadIdx.x;
    if (e < E) atomicAdd(&deg[dst[e]], 1);
}

__global__ void dinv_kernel(const int* __restrict__ deg, float* __restrict__ dinv, int N) {
    int i = blockIdx.x * blockDim.x + threadIdx.x;
    if (i < N) dinv[i] = rsqrtf((float)(deg[i] + 1));  // +1 self-loop
}

// ---------------- dense GEMM: H[N,COUT] = X[N,128] @ W[128,COUT] --------------
// Block: 256 threads, 24 rows x 64 cols per block. W column-slice in SMEM
// (k-major, conflict-free scalar broadcast-free loads), X rows in SMEM
// (float4, warp-uniform broadcast loads).
template<int COUT>
__global__ __launch_bounds__(256) void gemm_kernel(
    const float* __restrict__ X, const float* __restrict__ W,
    float* __restrict__ H, int N)
{
    constexpr int ROWS = 24;
    __shared__ float Ws[128 * 64];          // Ws[k*64 + c]
    __shared__ float Xs[ROWS * 128];        // Xs[r*128 + k]

    const int c0    = blockIdx.y * 64;
    const int rbase = blockIdx.x * ROWS;
    const int tid   = threadIdx.x;

    // load W slice [128, 64]
    #pragma unroll
    for (int i = tid; i < 128 * 64; i += 256) {
        int k = i >> 6, c = i & 63;
        Ws[i] = W[k * COUT + c0 + c];
    }
    // load X rows [ROWS, 128]
    #pragma unroll
    for (int i = tid; i < ROWS * 128; i += 256) {
        int r  = i >> 7;
        int gr = rbase + r;
        Xs[i] = (gr < N) ? X[(size_t)gr * 128 + (i & 127)] : 0.f;
    }
    __syncthreads();

    const int c = tid & 63;         // output column within slice
    const int g = tid >> 6;         // row group 0..3, 6 rows each
    float acc[6] = {0.f, 0.f, 0.f, 0.f, 0.f, 0.f};

    const float4* Xs4 = reinterpret_cast<const float4*>(Xs);
    #pragma unroll
    for (int k4 = 0; k4 < 32; ++k4) {
        float w0 = Ws[(k4 * 4 + 0) * 64 + c];
        float w1 = Ws[(k4 * 4 + 1) * 64 + c];
        float w2 = Ws[(k4 * 4 + 2) * 64 + c];
        float w3 = Ws[(k4 * 4 + 3) * 64 + c];
        #pragma unroll
        for (int j = 0; j < 6; ++j) {
            float4 xv = Xs4[(g * 6 + j) * 32 + k4];   // warp-uniform -> broadcast
            acc[j] += xv.x * w0;
            acc[j] += xv.y * w1;
            acc[j] += xv.z * w2;
            acc[j] += xv.w * w3;
        }
    }

    #pragma unroll
    for (int j = 0; j < 6; ++j) {
        int gr = rbase + g * 6 + j;
        if (gr < N) H[(size_t)gr * COUT + c0 + c] = acc[j];
    }
}

// ---------------- edge scatter, 128 features: one warp per edge --------------
__global__ void scatter128_kernel(
    const float* __restrict__ h, const int* __restrict__ src,
    const int* __restrict__ dst, const float* __restrict__ dinv,
    float* __restrict__ agg, int E)
{
    int gt   = blockIdx.x * blockDim.x + threadIdx.x;
    int e    = gt >> 5;
    int lane = gt & 31;
    if (e >= E) return;
    int s = src[e];
    int d = dst[e];
    float norm = dinv[s] * dinv[d];
    float4 v = reinterpret_cast<const float4*>(h + (size_t)s * 128)[lane];
    v.x *= norm; v.y *= norm; v.z *= norm; v.w *= norm;
    float* ap = agg + (size_t)d * 128 + lane * 4;
    asm volatile("red.global.add.v4.f32 [%0], {%1,%2,%3,%4};"
                 :: "l"(ap), "f"(v.x), "f"(v.y), "f"(v.z), "f"(v.w) : "memory");
}

// ---------------- edge scatter, 64 features: 16 threads per edge -------------
__global__ void scatter64_kernel(
    const float* __restrict__ h, const int* __restrict__ src,
    const int* __restrict__ dst, const float* __restrict__ dinv,
    float* __restrict__ agg, int E)
{
    int gt = blockIdx.x * blockDim.x + threadIdx.x;
    int e  = gt >> 4;
    int t  = gt & 15;
    if (e >= E) return;
    int s = src[e];
    int d = dst[e];
    float norm = dinv[s] * dinv[d];
    float4 v = reinterpret_cast<const float4*>(h + (size_t)s * 64)[t];
    v.x *= norm; v.y *= norm; v.z *= norm; v.w *= norm;
    float* ap = agg + (size_t)d * 64 + t * 4;
    asm volatile("red.global.add.v4.f32 [%0], {%1,%2,%3,%4};"
                 :: "l"(ap), "f"(v.x), "f"(v.y), "f"(v.z), "f"(v.w) : "memory");
}

// ---------------- finalize: out = agg + dinv^2 * h + b  (optional relu) ------
// COLS4 = number of float4 per row (32 for 128 feats, 16 for 64 feats)
template<int COLS4, bool RELU>
__global__ void finalize_kernel(
    float* __restrict__ out, const float* __restrict__ agg,
    const float* __restrict__ h, const float* __restrict__ dinv,
    const float* __restrict__ b, int N)
{
    int idx = blockIdx.x * blockDim.x + threadIdx.x;   // over N*COLS4
    if (idx >= N * COLS4) return;
    int i  = idx / COLS4;
    int c4 = idx - i * COLS4;
    float di = dinv[i];
    float s  = di * di;
    float4 a  = reinterpret_cast<const float4*>(agg)[idx];
    float4 hv = reinterpret_cast<const float4*>(h)[idx];
    float4 bv = reinterpret_cast<const float4*>(b)[c4];
    float4 r;
    r.x = a.x + s * hv.x + bv.x;
    r.y = a.y + s * hv.y + bv.y;
    r.z = a.z + s * hv.z + bv.z;
    r.w = a.w + s * hv.w + bv.w;
    if (RELU) {
        r.x = fmaxf(r.x, 0.f); r.y = fmaxf(r.y, 0.f);
        r.z = fmaxf(r.z, 0.f); r.w = fmaxf(r.w, 0.f);
    }
    reinterpret_cast<float4*>(out)[idx] = r;
}

// -----------------------------------------------------------------------------
extern "C" void kernel_launch(void* const* d_in, const int* in_sizes, int n_in,
                              void* d_out, int out_size)
{
    const float* x  = (const float*)d_in[0];
    const int*   ei = (const int*)  d_in[1];
    const float* W1 = (const float*)d_in[2];
    const float* b1 = (const float*)d_in[3];
    const float* W2 = (const float*)d_in[4];
    const float* b2 = (const float*)d_in[5];
    float* out = (float*)d_out;

    const int hid1 = in_sizes[3];            // 128
    const int feat = in_sizes[2] / hid1;     // 128
    const int N    = in_sizes[0] / feat;     // 50000
    const int E    = in_sizes[1] / 2;        // 800000
    const int* src = ei;
    const int* dst = ei + E;

    void *p_h1, *p_agg1, *p_h2, *p_deg, *p_dinv;
    cudaGetSymbolAddress(&p_h1,   g_h1);
    cudaGetSymbolAddress(&p_agg1, g_agg1);
    cudaGetSymbolAddress(&p_h2,   g_h2);
    cudaGetSymbolAddress(&p_deg,  g_deg);
    cudaGetSymbolAddress(&p_dinv, g_dinv);
    float* h1   = (float*)p_h1;
    float* agg1 = (float*)p_agg1;
    float* h2   = (float*)p_h2;
    int*   deg  = (int*)  p_deg;
    float* dinv = (float*)p_dinv;

    const int T = 256;

    // 1) degree + dinv (shared by both layers)
    zero_i_kernel<<<(N + T - 1) / T, T>>>(deg, N);
    count_deg_kernel<<<(E + T - 1) / T, T>>>(dst, deg, E);
    dinv_kernel<<<(N + T - 1) / T, T>>>(deg, dinv, N);

    // 2) layer 1: h1 = x @ W1
    {
        dim3 grid((N + 23) / 24, HID1 / 64);
        gemm_kernel<HID1><<<grid, 256>>>(x, W1, h1, N);
    }
    // 3) zero agg1, scatter edges, finalize (+self loop, +bias, relu) in place
    {
        int n4 = N * (HID1 / 4);
        zero_f4_kernel<<<(n4 + T - 1) / T, T>>>((float4*)agg1, n4);
        long long nt = (long long)E * 32;
        scatter128_kernel<<<(int)((nt + T - 1) / T), T>>>(h1, src, dst, dinv, agg1, E);
        int nf = N * (HID1 / 4);
        finalize_kernel<HID1 / 4, true><<<(nf + T - 1) / T, T>>>(agg1, agg1, h1, dinv, b1, N);
    }

    // 4) layer 2: h2 = agg1 @ W2
    {
        dim3 grid((N + 23) / 24, HID2 / 64);
        gemm_kernel<HID2><<<grid, 256>>>(agg1, W2, h2, N);
    }
    // 5) zero out, scatter edges into d_out, finalize (no relu)
    {
        int n4 = N * (HID2 / 4);
        zero_f4_kernel<<<(n4 + T - 1) / T, T>>>((float4*)out, n4);
        long long nt = (long long)E * 16;
        scatter64_kernel<<<(int)((nt + T - 1) / T), T>>>(h2, src, dst, dinv, out, E);
        int nf = N * (HID2 / 4);
        finalize_kernel<HID2 / 4, false><<<(nf + T - 1) / T, T>>>(out, out, h2, dinv, b2, N);
    }
}

// round 2
// speedup vs baseline: 1.0421x; 1.0421x over previous
#include <cuda_runtime.h>
#include <cuda_bf16.h>
#include <cstdint>

typedef unsigned long long ull;

// Problem constants (GCL_GCN: N=50000, E=800000, FEAT=128, HID1=128, HID2=64)
#define N_MAX   50000
#define FEAT    128
#define HID1    128
#define HID2    64

// ---------------- scratch (static device globals; no allocation) -------------
__device__ float g_h1  [(size_t)N_MAX * HID1];   // X @ W1
__device__ float g_agg1[(size_t)N_MAX * HID1];   // self-init + scatter target (layer 1)
__device__ float g_h2  [(size_t)N_MAX * HID2];   // relu(agg1) @ W2
__device__ int   g_deg [N_MAX];
__device__ float g_dinv[N_MAX];

// ---------------- f32x2 helpers (sm_103a packed fp32 FMA) --------------------
__device__ __forceinline__ ull pack2(float lo, float hi) {
    ull r;
    asm("mov.b64 %0, {%1, %2};" : "=l"(r) : "f"(lo), "f"(hi));
    return r;
}
__device__ __forceinline__ void unpack2(ull v, float& lo, float& hi) {
    asm("mov.b64 {%0, %1}, %2;" : "=f"(lo), "=f"(hi) : "l"(v));
}
__device__ __forceinline__ void fma2(ull& d, ull a, ull b) {
    asm("fma.rn.f32x2 %0, %1, %2, %3;" : "=l"(d) : "l"(a), "l"(b), "l"(d));
}

// ---------------- tiny utility kernels ---------------------------------------
__global__ void zero_i_kernel(int* __restrict__ p, int n) {
    int i = blockIdx.x * blockDim.x + threadIdx.x;
    if (i < n) p[i] = 0;
}

__global__ void count_deg_kernel(const int* __restrict__ dst, int* __restrict__ deg, int E) {
    int e = blockIdx.x * blockDim.x + threadIdx.x;
    if (e < E) atomicAdd(&deg[dst[e]], 1);
}

__global__ void dinv_kernel(const int* __restrict__ deg, float* __restrict__ dinv, int N) {
    int i = blockIdx.x * blockDim.x + threadIdx.x;
    if (i < N) dinv[i] = rsqrtf((float)(deg[i] + 1));  // +1 self-loop
}

// ---------------- fused GEMM: H = act(X)[N,128] @ W[128,COUT] -----------------
//                  AGG = dinv^2 * H + b   (self-loop init for the scatter)
// Block: 256 threads (16 tx x 16 ty). Tile: 128 rows x 64 cols.
// Thread: 8 rows x 4 cols, f32x2 accumulation over k-parity pairs.
// Xs row-major [128][130] (pad 2 floats keeps 8B align + dodges bank clash
// between the two ty row-groups of a warp). Ws [128][64].
#define XS_STRIDE 130
#define GEMM_SMEM ((128 * XS_STRIDE + 128 * 64) * 4)

template<int COUT, bool RELU_IN>
__global__ __launch_bounds__(256) void gemm_f32x2_kernel(
    const float* __restrict__ X, const float* __restrict__ W,
    const float* __restrict__ dinv, const float* __restrict__ bias,
    float* __restrict__ H, float* __restrict__ AGG, int N)
{
    extern __shared__ float sm[];
    float* Xs = sm;                       // [128][XS_STRIDE]
    float* Ws = sm + 128 * XS_STRIDE;     // [128][64]

    const int tid   = threadIdx.x;
    const int tx    = tid & 15;           // 16 col groups (4 cols each)
    const int ty    = tid >> 4;           // 16 row groups (8 rows each)
    const int rbase = blockIdx.x * 128;
    const int c0    = 4 * tx;             // col within 64-slice
    const int gslice= blockIdx.y * 64;    // global col base of slice

    // ---- load W slice [128, 64] (float4, coalesced) ----
    const float4* Wg4 = reinterpret_cast<const float4*>(W);
    float4* Ws4 = reinterpret_cast<float4*>(Ws);
    #pragma unroll
    for (int it = 0; it < 8; ++it) {                  // 2048 float4 / 256 thr
        int i = tid + it * 256;
        int k = i >> 4, c4 = i & 15;                  // 16 float4 per row
        Ws4[i] = Wg4[k * (COUT / 4) + (gslice / 4) + c4];
    }

    // ---- load X tile [128 rows, 128 k] (coalesced gmem, 2x STS.64) ----
    const float4* Xg4 = reinterpret_cast<const float4*>(X);
    #pragma unroll
    for (int it = 0; it < 16; ++it) {                 // 4096 float4 / 256 thr
        int i  = tid + it * 256;
        int r  = i >> 5, k4 = i & 31;                 // 32 float4 per row
        int gr = rbase + r;
        float4 v = make_float4(0.f, 0.f, 0.f, 0.f);
        if (gr < N) v = Xg4[(size_t)gr * 32 + k4];
        if (RELU_IN) {
            v.x = fmaxf(v.x, 0.f); v.y = fmaxf(v.y, 0.f);
            v.z = fmaxf(v.z, 0.f); v.w = fmaxf(v.w, 0.f);
        }
        ull* dst64 = reinterpret_cast<ull*>(&Xs[r * XS_STRIDE + k4 * 4]);
        dst64[0] = pack2(v.x, v.y);
        dst64[1] = pack2(v.z, v.w);
    }
    __syncthreads();

    // ---- main loop: f32x2 over k-pairs ----
    ull acc[8][4];
    #pragma unroll
    for (int i = 0; i < 8; ++i)
        #pragma unroll
        for (int j = 0; j < 4; ++j) acc[i][j] = 0ull;

    #pragma unroll 4
    for (int k = 0; k < 128; k += 2) {
        float4 wk  = *reinterpret_cast<const float4*>(&Ws[k * 64 + c0]);
        float4 wk1 = *reinterpret_cast<const float4*>(&Ws[(k + 1) * 64 + c0]);
        ull w2[4];
        w2[0] = pack2(wk.x, wk1.x);
        w2[1] = pack2(wk.y, wk1.y);
        w2[2] = pack2(wk.z, wk1.z);
        w2[3] = pack2(wk.w, wk1.w);
        #pragma unroll
        for (int i = 0; i < 8; ++i) {
            ull xv = *reinterpret_cast<const ull*>(&Xs[(ty * 8 + i) * XS_STRIDE + k]);
            #pragma unroll
            for (int j = 0; j < 4; ++j) fma2(acc[i][j], xv, w2[j]);
        }
    }

    // ---- epilogue: write H and AGG = dinv^2 * H + b ----
    const float4 bv = reinterpret_cast<const float4*>(bias)[(gslice + c0) / 4];
    #pragma unroll
    for (int i = 0; i < 8; ++i) {
        int gr = rbase + ty * 8 + i;
        if (gr >= N) continue;
        float lo, hi;
        float4 hv;
        unpack2(acc[i][0], lo, hi); hv.x = lo + hi;
        unpack2(acc[i][1], lo, hi); hv.y = lo + hi;
        unpack2(acc[i][2], lo, hi); hv.z = lo + hi;
        unpack2(acc[i][3], lo, hi); hv.w = lo + hi;
        float di = dinv[gr];
        float s  = di * di;
        size_t off4 = (size_t)gr * (COUT / 4) + (gslice + c0) / 4;
        reinterpret_cast<float4*>(H)[off4] = hv;
        float4 av;
        av.x = fmaf(s, hv.x, bv.x);
        av.y = fmaf(s, hv.y, bv.y);
        av.z = fmaf(s, hv.z, bv.z);
        av.w = fmaf(s, hv.w, bv.w);
        reinterpret_cast<float4*>(AGG)[off4] = av;
    }
}

// ---------------- edge scatter, 128 features: one warp per edge --------------
__global__ void scatter128_kernel(
    const float* __restrict__ h, const int* __restrict__ src,
    const int* __restrict__ dst, const float* __restrict__ dinv,
    float* __restrict__ agg, int E)
{
    int gt   = blockIdx.x * blockDim.x + threadIdx.x;
    int e    = gt >> 5;
    int lane = gt & 31;
    if (e >= E) return;
    int s = src[e];
    int d = dst[e];
    float norm = dinv[s] * dinv[d];
    float4 v = reinterpret_cast<const float4*>(h + (size_t)s * 128)[lane];
    v.x *= norm; v.y *= norm; v.z *= norm; v.w *= norm;
    float* ap = agg + (size_t)d * 128 + lane * 4;
    asm volatile("red.global.add.v4.f32 [%0], {%1,%2,%3,%4};"
                 :: "l"(ap), "f"(v.x), "f"(v.y), "f"(v.z), "f"(v.w) : "memory");
}

// ---------------- edge scatter, 64 features: 16 threads per edge -------------
__global__ void scatter64_kernel(
    const float* __restrict__ h, const int* __restrict__ src,
    const int* __restrict__ dst, const float* __restrict__ dinv,
    float* __restrict__ agg, int E)
{
    int gt = blockIdx.x * blockDim.x + threadIdx.x;
    int e  = gt >> 4;
    int t  = gt & 15;
    if (e >= E) return;
    int s = src[e];
    int d = dst[e];
    float norm = dinv[s] * dinv[d];
    float4 v = reinterpret_cast<const float4*>(h + (size_t)s * 64)[t];
    v.x *= norm; v.y *= norm; v.z *= norm; v.w *= norm;
    float* ap = agg + (size_t)d * 64 + t * 4;
    asm volatile("red.global.add.v4.f32 [%0], {%1,%2,%3,%4};"
                 :: "l"(ap), "f"(v.x), "f"(v.y), "f"(v.z), "f"(v.w) : "memory");
}

// -----------------------------------------------------------------------------
extern "C" void kernel_launch(void* const* d_in, const int* in_sizes, int n_in,
                              void* d_out, int out_size)
{
    const float* x  = (const float*)d_in[0];
    const int*   ei = (const int*)  d_in[1];
    const float* W1 = (const float*)d_in[2];
    const float* b1 = (const float*)d_in[3];
    const float* W2 = (const float*)d_in[4];
    const float* b2 = (const float*)d_in[5];
    float* out = (float*)d_out;

    const int hid1 = in_sizes[3];            // 128
    const int feat = in_sizes[2] / hid1;     // 128
    const int N    = in_sizes[0] / feat;     // 50000
    const int E    = in_sizes[1] / 2;        // 800000
    const int* src = ei;
    const int* dst = ei + E;

    void *p_h1, *p_agg1, *p_h2, *p_deg, *p_dinv;
    cudaGetSymbolAddress(&p_h1,   g_h1);
    cudaGetSymbolAddress(&p_agg1, g_agg1);
    cudaGetSymbolAddress(&p_h2,   g_h2);
    cudaGetSymbolAddress(&p_deg,  g_deg);
    cudaGetSymbolAddress(&p_dinv, g_dinv);
    float* h1   = (float*)p_h1;
    float* agg1 = (float*)p_agg1;
    float* h2   = (float*)p_h2;
    int*   deg  = (int*)  p_deg;
    float* dinv = (float*)p_dinv;

    // opt-in to >48KB dynamic smem (host-side attribute set; not a stream op)
    static bool attr_done = false;
    if (!attr_done) {
        cudaFuncSetAttribute(gemm_f32x2_kernel<HID1, false>,
                             cudaFuncAttributeMaxDynamicSharedMemorySize, GEMM_SMEM);
        cudaFuncSetAttribute(gemm_f32x2_kernel<HID2, true>,
                             cudaFuncAttributeMaxDynamicSharedMemorySize, GEMM_SMEM);
        attr_done = true;
    }

    const int T = 256;

    // 1) degree + dinv (shared by both layers)
    zero_i_kernel<<<(N + T - 1) / T, T>>>(deg, N);
    count_deg_kernel<<<(E + T - 1) / T, T>>>(dst, deg, E);
    dinv_kernel<<<(N + T - 1) / T, T>>>(deg, dinv, N);

    const int gx = (N + 127) / 128;

    // 2) layer 1 GEMM (fused: h1 = x@W1 ; agg1 = dinv^2*h1 + b1)
    {
        dim3 grid(gx, HID1 / 64);
        gemm_f32x2_kernel<HID1, false><<<grid, 256, GEMM_SMEM>>>(
            x, W1, dinv, b1, h1, agg1, N);
    }
    // 3) scatter edges into agg1
    {
        long long nt = (long long)E * 32;
        scatter128_kernel<<<(int)((nt + T - 1) / T), T>>>(h1, src, dst, dinv, agg1, E);
    }
    // 4) layer 2 GEMM (relu on load; fused: h2 = relu(agg1)@W2 ; out = dinv^2*h2 + b2)
    {
        dim3 grid(gx, HID2 / 64);
        gemm_f32x2_kernel<HID2, true><<<grid, 256, GEMM_SMEM>>>(
            agg1, W2, dinv, b2, h2, out, N);
    }
    // 5) scatter edges into out
    {
        long long nt = (long long)E * 16;
        scatter64_kernel<<<(int)((nt + T - 1) / T), T>>>(h2, src, dst, dinv, out, E);
    }
}

// round 3
// speedup vs baseline: 1.5572x; 1.4943x over previous
#include <cuda_runtime.h>
#include <cuda_bf16.h>
#include <cstdint>

typedef unsigned long long ull;

// Problem constants (GCL_GCN: N=50000, E=800000, FEAT=128, HID1=128, HID2=64)
#define N_MAX   50000
#define E_MAX   800000
#define HID1    128
#define HID2    64

// ---------------- scratch (static device globals; no allocation) -------------
__device__ float g_h1  [(size_t)N_MAX * HID1];   // dinv * (X @ W1)
__device__ float g_a1  [(size_t)N_MAX * HID1];   // relu(aggregated layer1)
__device__ float g_h2  [(size_t)N_MAX * HID2];   // dinv * (a1 @ W2)
__device__ int   g_deg [N_MAX];
__device__ float g_dinv[N_MAX];
__device__ int   g_rowstart[N_MAX + 1];
__device__ int   g_cursor  [N_MAX];
__device__ int   g_csrc    [E_MAX];              // edges sorted by dst -> src ids

// ---------------- f32x2 helpers (sm_103a packed fp32 FMA) --------------------
__device__ __forceinline__ ull pack2(float lo, float hi) {
    ull r;
    asm("mov.b64 %0, {%1, %2};" : "=l"(r) : "f"(lo), "f"(hi));
    return r;
}
__device__ __forceinline__ void unpack2(ull v, float& lo, float& hi) {
    asm("mov.b64 {%0, %1}, %2;" : "=f"(lo), "=f"(hi) : "l"(v));
}
__device__ __forceinline__ void fma2(ull& d, ull a, ull b) {
    asm("fma.rn.f32x2 %0, %1, %2, %3;" : "=l"(d) : "l"(a), "l"(b), "l"(d));
}

// ---------------- degree / dinv ----------------------------------------------
__global__ void zero_i_kernel(int* __restrict__ p, int n) {
    int i = blockIdx.x * blockDim.x + threadIdx.x;
    if (i < n) p[i] = 0;
}
__global__ void count_deg_kernel(const int* __restrict__ dst, int* __restrict__ deg, int E) {
    int e = blockIdx.x * blockDim.x + threadIdx.x;
    if (e < E) atomicAdd(&deg[dst[e]], 1);
}
__global__ void dinv_kernel(const int* __restrict__ deg, float* __restrict__ dinv, int N) {
    int i = blockIdx.x * blockDim.x + threadIdx.x;
    if (i < N) dinv[i] = rsqrtf((float)(deg[i] + 1));  // +1 self-loop
}

// ---------------- single-block exclusive scan (deg -> row_start, cursor) -----
__global__ __launch_bounds__(1024) void scan_kernel(
    const int* __restrict__ deg, int* __restrict__ row_start,
    int* __restrict__ cursor, int N)
{
    __shared__ int warp_sums[32];
    __shared__ int s_offset;
    const int lane = threadIdx.x & 31;
    const int wid  = threadIdx.x >> 5;
    if (threadIdx.x == 0) s_offset = 0;
    __syncthreads();

    for (int base = 0; base < N; base += 1024) {
        int i = base + (int)threadIdx.x;
        int v = (i < N) ? deg[i] : 0;
        int x = v;
        #pragma unroll
        for (int o = 1; o < 32; o <<= 1) {
            int t = __shfl_up_sync(0xffffffffu, x, o);
            if (lane >= o) x += t;
        }
        if (lane == 31) warp_sums[wid] = x;
        __syncthreads();
        if (wid == 0) {
            int ws = warp_sums[lane];
            #pragma unroll
            for (int o = 1; o < 32; o <<= 1) {
                int t = __shfl_up_sync(0xffffffffu, ws, o);
                if (lane >= o) ws += t;
            }
            warp_sums[lane] = ws;
        }
        __syncthreads();
        int excl = x - v + (wid > 0 ? warp_sums[wid - 1] : 0) + s_offset;
        if (i < N) { row_start[i] = excl; cursor[i] = excl; }
        __syncthreads();
        if (threadIdx.x == 0) s_offset += warp_sums[31];
        __syncthreads();
    }
    if (threadIdx.x == 0) row_start[N] = s_offset;
}

// ---------------- fill CSR: csrc sorted by dst --------------------------------
__global__ void fill_csr_kernel(
    const int* __restrict__ src, const int* __restrict__ dst,
    int* __restrict__ cursor, int* __restrict__ csrc, int E)
{
    int e = blockIdx.x * blockDim.x + threadIdx.x;
    if (e < E) {
        int pos = atomicAdd(&cursor[dst[e]], 1);
        csrc[pos] = src[e];
    }
}

// ---------------- fused GEMM: Hs = dinv * (X[N,128] @ W[128,COUT]) ------------
// Block: 256 threads (16 tx x 16 ty). Tile: 128 rows x 64 cols.
// Thread: 8 rows x 4 cols. f32x2 over k-parity pairs; W pre-packed in SMEM.
#define GEMM_SMEM ((128 * 64 + 64 * 64) * 8)   // Xs2 + Ws2, ull each

template<int COUT>
__global__ __launch_bounds__(256) void gemm_f32x2_kernel(
    const float* __restrict__ X, const float* __restrict__ W,
    const float* __restrict__ dinv, float* __restrict__ Hs, int N)
{
    extern __shared__ ull sm2[];
    ull* Xs2 = sm2;                 // [128][64]  (row r, k-pair k2)
    ull* Ws2 = sm2 + 128 * 64;      // [64][64]   (k-pair k2, col c)

    const int tid    = threadIdx.x;
    const int tx     = tid & 15;            // 16 col groups (4 cols each)
    const int ty     = tid >> 4;            // 16 row groups (8 rows each)
    const int rbase  = blockIdx.x * 128;
    const int c0     = 4 * tx;
    const int gslice = blockIdx.y * 64;

    // ---- prepack W slice [128,64] -> Ws2[k2][c] = (W[2k2][c], W[2k2+1][c]) ----
    #pragma unroll
    for (int it = 0; it < 16; ++it) {       // 4096 ull / 256 thr
        int i  = tid + it * 256;
        int k2 = i >> 6, c = i & 63;
        float w0 = W[(2 * k2)     * COUT + gslice + c];
        float w1 = W[(2 * k2 + 1) * COUT + gslice + c];
        Ws2[i] = pack2(w0, w1);
    }

    // ---- load X tile [128 rows, 128 k] (coalesced float4 -> 2x ull) ----
    const float4* Xg4 = reinterpret_cast<const float4*>(X);
    #pragma unroll
    for (int it = 0; it < 16; ++it) {       // 4096 float4 / 256 thr
        int i  = tid + it * 256;
        int r  = i >> 5, k4 = i & 31;
        int gr = rbase + r;
        float4 v = make_float4(0.f, 0.f, 0.f, 0.f);
        if (gr < N) v = Xg4[(size_t)gr * 32 + k4];
        Xs2[r * 64 + k4 * 2 + 0] = pack2(v.x, v.y);
        Xs2[r * 64 + k4 * 2 + 1] = pack2(v.z, v.w);
    }
    __syncthreads();

    // ---- main loop over 64 k-pairs ----
    ull acc[8][4];
    #pragma unroll
    for (int i = 0; i < 8; ++i)
        #pragma unroll
        for (int j = 0; j < 4; ++j) acc[i][j] = 0ull;

    const ull* xrow = Xs2 + ty * 8 * 64;
    const ull* wrow = Ws2 + c0;
    #pragma unroll 8
    for (int k2 = 0; k2 < 64; ++k2) {
        ull w2[4];
        #pragma unroll
        for (int j = 0; j < 4; ++j) w2[j] = wrow[k2 * 64 + j];
        #pragma unroll
        for (int i = 0; i < 8; ++i) {
            ull xv = xrow[i * 64 + k2];
            #pragma unroll
            for (int j = 0; j < 4; ++j) fma2(acc[i][j], xv, w2[j]);
        }
    }

    // ---- epilogue: Hs = dinv * (lo + hi) ----
    #pragma unroll
    for (int i = 0; i < 8; ++i) {
        int gr = rbase + ty * 8 + i;
        if (gr >= N) continue;
        float di = dinv[gr];
        float lo, hi;
        float4 hv;
        unpack2(acc[i][0], lo, hi); hv.x = (lo + hi) * di;
        unpack2(acc[i][1], lo, hi); hv.y = (lo + hi) * di;
        unpack2(acc[i][2], lo, hi); hv.z = (lo + hi) * di;
        unpack2(acc[i][3], lo, hi); hv.w = (lo + hi) * di;
        reinterpret_cast<float4*>(Hs)[(size_t)gr * (COUT / 4) + (gslice + c0) / 4] = hv;
    }
}

// ---------------- CSR gather, 128 feats: one warp per node -------------------
// out[d] = act( dinv[d] * (sum_{nbr} hs[s] + hs[d]) + b )
template<bool RELU>
__global__ __launch_bounds__(256) void gather128_kernel(
    const float* __restrict__ hs, const int* __restrict__ rs,
    const int* __restrict__ csrc, const float* __restrict__ dinv,
    const float* __restrict__ b, float* __restrict__ out, int N)
{
    int node = (blockIdx.x * blockDim.x + threadIdx.x) >> 5;
    int lane = threadIdx.x & 31;
    if (node >= N) return;
    int beg = rs[node], end = rs[node + 1];
    const float4* h4 = reinterpret_cast<const float4*>(hs);

    float4 a0 = h4[(size_t)node * 32 + lane];   // self (already dinv-scaled)
    float4 a1 = make_float4(0.f, 0.f, 0.f, 0.f);
    int j = beg;
    for (; j + 1 < end; j += 2) {
        int s0 = csrc[j], s1 = csrc[j + 1];
        float4 v0 = h4[(size_t)s0 * 32 + lane];
        float4 v1 = h4[(size_t)s1 * 32 + lane];
        a0.x += v0.x; a0.y += v0.y; a0.z += v0.z; a0.w += v0.w;
        a1.x += v1.x; a1.y += v1.y; a1.z += v1.z; a1.w += v1.w;
    }
    if (j < end) {
        int s0 = csrc[j];
        float4 v0 = h4[(size_t)s0 * 32 + lane];
        a0.x += v0.x; a0.y += v0.y; a0.z += v0.z; a0.w += v0.w;
    }
    float dd = dinv[node];
    float4 bv = reinterpret_cast<const float4*>(b)[lane];
    float4 r;
    r.x = fmaf(dd, a0.x + a1.x, bv.x);
    r.y = fmaf(dd, a0.y + a1.y, bv.y);
    r.z = fmaf(dd, a0.z + a1.z, bv.z);
    r.w = fmaf(dd, a0.w + a1.w, bv.w);
    if (RELU) {
        r.x = fmaxf(r.x, 0.f); r.y = fmaxf(r.y, 0.f);
        r.z = fmaxf(r.z, 0.f); r.w = fmaxf(r.w, 0.f);
    }
    reinterpret_cast<float4*>(out)[(size_t)node * 32 + lane] = r;
}

// ---------------- CSR gather, 64 feats: one warp per node (float2/lane) ------
__global__ __launch_bounds__(256) void gather64_kernel(
    const float* __restrict__ hs, const int* __restrict__ rs,
    const int* __restrict__ csrc, const float* __restrict__ dinv,
    const float* __restrict__ b, float* __restrict__ out, int N)
{
    int node = (blockIdx.x * blockDim.x + threadIdx.x) >> 5;
    int lane = threadIdx.x & 31;
    if (node >= N) return;
    int beg = rs[node], end = rs[node + 1];
    const float2* h2 = reinterpret_cast<const float2*>(hs);

    float2 a0 = h2[(size_t)node * 32 + lane];
    float2 a1 = make_float2(0.f, 0.f);
    int j = beg;
    for (; j + 1 < end; j += 2) {
        int s0 = csrc[j], s1 = csrc[j + 1];
        float2 v0 = h2[(size_t)s0 * 32 + lane];
        float2 v1 = h2[(size_t)s1 * 32 + lane];
        a0.x += v0.x; a0.y += v0.y;
        a1.x += v1.x; a1.y += v1.y;
    }
    if (j < end) {
        int s0 = csrc[j];
        float2 v0 = h2[(size_t)s0 * 32 + lane];
        a0.x += v0.x; a0.y += v0.y;
    }
    float dd = dinv[node];
    float2 bv = reinterpret_cast<const float2*>(b)[lane];
    float2 r;
    r.x = fmaf(dd, a0.x + a1.x, bv.x);
    r.y = fmaf(dd, a0.y + a1.y, bv.y);
    reinterpret_cast<float2*>(out)[(size_t)node * 32 + lane] = r;
}

// -----------------------------------------------------------------------------
extern "C" void kernel_launch(void* const* d_in, const int* in_sizes, int n_in,
                              void* d_out, int out_size)
{
    const float* x  = (const float*)d_in[0];
    const int*   ei = (const int*)  d_in[1];
    const float* W1 = (const float*)d_in[2];
    const float* b1 = (const float*)d_in[3];
    const float* W2 = (const float*)d_in[4];
    const float* b2 = (const float*)d_in[5];
    float* out = (float*)d_out;

    const int hid1 = in_sizes[3];            // 128
    const int feat = in_sizes[2] / hid1;     // 128
    const int N    = in_sizes[0] / feat;     // 50000
    const int E    = in_sizes[1] / 2;        // 800000
    const int* src = ei;
    const int* dst = ei + E;

    void *p_h1, *p_a1, *p_h2, *p_deg, *p_dinv, *p_rs, *p_cur, *p_csrc;
    cudaGetSymbolAddress(&p_h1,   g_h1);
    cudaGetSymbolAddress(&p_a1,   g_a1);
    cudaGetSymbolAddress(&p_h2,   g_h2);
    cudaGetSymbolAddress(&p_deg,  g_deg);
    cudaGetSymbolAddress(&p_dinv, g_dinv);
    cudaGetSymbolAddress(&p_rs,   g_rowstart);
    cudaGetSymbolAddress(&p_cur,  g_cursor);
    cudaGetSymbolAddress(&p_csrc, g_csrc);
    float* h1   = (float*)p_h1;
    float* a1   = (float*)p_a1;
    float* h2   = (float*)p_h2;
    int*   deg  = (int*)  p_deg;
    float* dinv = (float*)p_dinv;
    int*   rs   = (int*)  p_rs;
    int*   cur  = (int*)  p_cur;
    int*   csrc = (int*)  p_csrc;

    static bool attr_done = false;
    if (!attr_done) {
        cudaFuncSetAttribute(gemm_f32x2_kernel<HID1>,
                             cudaFuncAttributeMaxDynamicSharedMemorySize, GEMM_SMEM);
        cudaFuncSetAttribute(gemm_f32x2_kernel<HID2>,
                             cudaFuncAttributeMaxDynamicSharedMemorySize, GEMM_SMEM);
        attr_done = true;
    }

    const int T = 256;

    // 1) degree + dinv + CSR build
    zero_i_kernel<<<(N + T - 1) / T, T>>>(deg, N);
    count_deg_kernel<<<(E + T - 1) / T, T>>>(dst, deg, E);
    dinv_kernel<<<(N + T - 1) / T, T>>>(deg, dinv, N);
    scan_kernel<<<1, 1024>>>(deg, rs, cur, N);
    fill_csr_kernel<<<(E + T - 1) / T, T>>>(src, dst, cur, csrc, E);

    const int gx = (N + 127) / 128;
    const int gwarp = (N * 32 + T - 1) / T;   // blocks for one-warp-per-node

    // 2) layer 1: h1 = dinv * (x @ W1)
    {
        dim3 grid(gx, HID1 / 64);
        gemm_f32x2_kernel<HID1><<<grid, 256, GEMM_SMEM>>>(x, W1, dinv, h1, N);
    }
    // 3) gather layer 1: a1 = relu(dinv * (sum nbr + self) + b1)
    gather128_kernel<true><<<gwarp, T>>>(h1, rs, csrc, dinv, b1, a1, N);

    // 4) layer 2: h2 = dinv * (a1 @ W2)
    {
        dim3 grid(gx, HID2 / 64);
        gemm_f32x2_kernel<HID2><<<grid, 256, GEMM_SMEM>>>(a1, W2, dinv, h2, N);
    }
    // 5) gather layer 2 into out (no relu)
    gather64_kernel<<<gwarp, T>>>(h2, rs, csrc, dinv, b2, out, N);
}

// round 4
// speedup vs baseline: 1.8329x; 1.1771x over previous
#include <cuda_runtime.h>
#include <cuda_bf16.h>
#include <cstdint>

typedef unsigned long long ull;

// Problem constants (GCL_GCN: N=50000, E=800000, FEAT=128, HID1=128, HID2=64)
#define N_MAX   50000
#define E_MAX   800000
#define HID1    128
#define HID2    64
#define SCAN_B  1024
#define SCAN_NBLOCKS ((N_MAX + SCAN_B - 1) / SCAN_B + 1)

// ---------------- scratch (static device globals; no allocation) -------------
__device__ float g_h1  [(size_t)N_MAX * HID1];   // dinv * (X @ W1)
__device__ float g_a1  [(size_t)N_MAX * HID1];   // relu(aggregated layer1)
__device__ float g_h2  [(size_t)N_MAX * HID2];   // dinv * (a1 @ W2)
__device__ int   g_deg [N_MAX];
__device__ float g_dinv[N_MAX];
__device__ int   g_rowstart[N_MAX + 1];
__device__ int   g_cursor  [N_MAX];
__device__ int   g_csrc    [E_MAX];              // edges sorted by dst -> src ids
__device__ int   g_bsum    [SCAN_NBLOCKS + 1];   // per-block scan sums

// ---------------- f32x2 helpers (sm_103a packed fp32 FMA) --------------------
__device__ __forceinline__ ull pack2(float lo, float hi) {
    ull r;
    asm("mov.b64 %0, {%1, %2};" : "=l"(r) : "f"(lo), "f"(hi));
    return r;
}
__device__ __forceinline__ void unpack2(ull v, float& lo, float& hi) {
    asm("mov.b64 {%0, %1}, %2;" : "=f"(lo), "=f"(hi) : "l"(v));
}
__device__ __forceinline__ void fma2(ull& d, ull a, ull b) {
    asm("fma.rn.f32x2 %0, %1, %2, %3;" : "=l"(d) : "l"(a), "l"(b), "l"(d));
}

// ---------------- degree / dinv ----------------------------------------------
__global__ void zero_i_kernel(int* __restrict__ p, int n) {
    int i = blockIdx.x * blockDim.x + threadIdx.x;
    if (i < n) p[i] = 0;
}
__global__ void count_deg_kernel(const int* __restrict__ dst, int* __restrict__ deg, int E) {
    int e = blockIdx.x * blockDim.x + threadIdx.x;
    if (e < E) atomicAdd(&deg[dst[e]], 1);
}
__global__ void dinv_kernel(const int* __restrict__ deg, float* __restrict__ dinv, int N) {
    int i = blockIdx.x * blockDim.x + threadIdx.x;
    if (i < N) dinv[i] = rsqrtf((float)(deg[i] + 1));  // +1 self-loop
}

// ---------------- multi-block exclusive scan ----------------------------------
// Phase A: per-block exclusive scan of deg -> row_start (local), block sum -> bsum
__global__ __launch_bounds__(SCAN_B) void scan_blocks_kernel(
    const int* __restrict__ deg, int* __restrict__ row_start,
    int* __restrict__ bsum, int N)
{
    __shared__ int warp_sums[32];
    const int lane = threadIdx.x & 31;
    const int wid  = threadIdx.x >> 5;
    int i = blockIdx.x * SCAN_B + threadIdx.x;
    int v = (i < N) ? deg[i] : 0;
    int x = v;
    #pragma unroll
    for (int o = 1; o < 32; o <<= 1) {
        int t = __shfl_up_sync(0xffffffffu, x, o);
        if (lane >= o) x += t;
    }
    if (lane == 31) warp_sums[wid] = x;
    __syncthreads();
    if (wid == 0) {
        int ws = warp_sums[lane];
        #pragma unroll
        for (int o = 1; o < 32; o <<= 1) {
            int t = __shfl_up_sync(0xffffffffu, ws, o);
            if (lane >= o) ws += t;
        }
        warp_sums[lane] = ws;
    }
    __syncthreads();
    int excl = x - v + (wid > 0 ? warp_sums[wid - 1] : 0);
    if (i < N) row_start[i] = excl;
    if (threadIdx.x == SCAN_B - 1) bsum[blockIdx.x] = excl + v;
}

// Phase B: single small block scans the block sums (nblocks <= 64)
__global__ __launch_bounds__(64) void scan_bsums_kernel(int* __restrict__ bsum, int nblocks) {
    const int lane = threadIdx.x & 31;
    const int wid  = threadIdx.x >> 5;
    __shared__ int wsum[2];
    int v = (threadIdx.x < nblocks) ? bsum[threadIdx.x] : 0;
    int x = v;
    #pragma unroll
    for (int o = 1; o < 32; o <<= 1) {
        int t = __shfl_up_sync(0xffffffffu, x, o);
        if (lane >= o) x += t;
    }
    if (lane == 31) wsum[wid] = x;
    __syncthreads();
    int excl = x - v + (wid > 0 ? wsum[0] : 0);
    if (threadIdx.x < nblocks) bsum[threadIdx.x] = excl;
    if (threadIdx.x == nblocks - 1) bsum[nblocks] = excl + v;  // grand total
}

// Phase C: add block offsets, produce cursor, and row_start[N]
__global__ __launch_bounds__(SCAN_B) void scan_add_kernel(
    int* __restrict__ row_start, int* __restrict__ cursor,
    const int* __restrict__ bsum, int N, int nblocks)
{
    int i = blockIdx.x * SCAN_B + threadIdx.x;
    if (i < N) {
        int r = row_start[i] + bsum[blockIdx.x];
        row_start[i] = r;
        cursor[i]    = r;
    }
    if (i == 0) row_start[N] = bsum[nblocks];
}

// ---------------- fill CSR: csrc sorted by dst --------------------------------
__global__ void fill_csr_kernel(
    const int* __restrict__ src, const int* __restrict__ dst,
    int* __restrict__ cursor, int* __restrict__ csrc, int E)
{
    int e = blockIdx.x * blockDim.x + threadIdx.x;
    if (e < E) {
        int pos = atomicAdd(&cursor[dst[e]], 1);
        csrc[pos] = src[e];
    }
}

// ---------------- fused GEMM: Hs = dinv * (X[N,128] @ W[128,COUT]) ------------
// Block: 256 threads (16 tx x 16 ty). Tile: 128 rows x 64 cols.
// Thread: 8 rows x 4 cols. f32x2 over k-parity pairs; W pre-packed in SMEM.
#define GEMM_SMEM ((128 * 64 + 64 * 64) * 8)   // Xs2 + Ws2, ull each

template<int COUT>
__global__ __launch_bounds__(256) void gemm_f32x2_kernel(
    const float* __restrict__ X, const float* __restrict__ W,
    const float* __restrict__ dinv, float* __restrict__ Hs, int N)
{
    extern __shared__ ull sm2[];
    ull* Xs2 = sm2;                 // [128][64]  (row r, k-pair k2)
    ull* Ws2 = sm2 + 128 * 64;      // [64][64]   (k-pair k2, col c)

    const int tid    = threadIdx.x;
    const int tx     = tid & 15;            // 16 col groups (4 cols each)
    const int ty     = tid >> 4;            // 16 row groups (8 rows each)
    const int rbase  = blockIdx.x * 128;
    const int c0     = 4 * tx;
    const int gslice = blockIdx.y * 64;

    // ---- prepack W slice [128,64] -> Ws2[k2][c] = (W[2k2][c], W[2k2+1][c]) ----
    #pragma unroll
    for (int it = 0; it < 16; ++it) {       // 4096 ull / 256 thr
        int i  = tid + it * 256;
        int k2 = i >> 6, c = i & 63;
        float w0 = W[(2 * k2)     * COUT + gslice + c];
        float w1 = W[(2 * k2 + 1) * COUT + gslice + c];
        Ws2[i] = pack2(w0, w1);
    }

    // ---- load X tile [128 rows, 128 k] (coalesced float4 -> 2x ull) ----
    const float4* Xg4 = reinterpret_cast<const float4*>(X);
    #pragma unroll
    for (int it = 0; it < 16; ++it) {       // 4096 float4 / 256 thr
        int i  = tid + it * 256;
        int r  = i >> 5, k4 = i & 31;
        int gr = rbase + r;
        float4 v = make_float4(0.f, 0.f, 0.f, 0.f);
        if (gr < N) v = Xg4[(size_t)gr * 32 + k4];
        Xs2[r * 64 + k4 * 2 + 0] = pack2(v.x, v.y);
        Xs2[r * 64 + k4 * 2 + 1] = pack2(v.z, v.w);
    }
    __syncthreads();

    // ---- main loop over 64 k-pairs ----
    ull acc[8][4];
    #pragma unroll
    for (int i = 0; i < 8; ++i)
        #pragma unroll
        for (int j = 0; j < 4; ++j) acc[i][j] = 0ull;

    const ull* xrow = Xs2 + ty * 8 * 64;
    const ull* wrow = Ws2 + c0;
    #pragma unroll 8
    for (int k2 = 0; k2 < 64; ++k2) {
        ull w2[4];
        #pragma unroll
        for (int j = 0; j < 4; ++j) w2[j] = wrow[k2 * 64 + j];
        #pragma unroll
        for (int i = 0; i < 8; ++i) {
            ull xv = xrow[i * 64 + k2];
            #pragma unroll
            for (int j = 0; j < 4; ++j) fma2(acc[i][j], xv, w2[j]);
        }
    }

    // ---- epilogue: Hs = dinv * (lo + hi) ----
    #pragma unroll
    for (int i = 0; i < 8; ++i) {
        int gr = rbase + ty * 8 + i;
        if (gr >= N) continue;
        float di = dinv[gr];
        float lo, hi;
        float4 hv;
        unpack2(acc[i][0], lo, hi); hv.x = (lo + hi) * di;
        unpack2(acc[i][1], lo, hi); hv.y = (lo + hi) * di;
        unpack2(acc[i][2], lo, hi); hv.z = (lo + hi) * di;
        unpack2(acc[i][3], lo, hi); hv.w = (lo + hi) * di;
        reinterpret_cast<float4*>(Hs)[(size_t)gr * (COUT / 4) + (gslice + c0) / 4] = hv;
    }
}

// ---------------- CSR gather, 128 feats: one warp per node -------------------
// out[d] = act( dinv[d] * (sum_{nbr} hs[s] + hs[d]) + b )
template<bool RELU>
__global__ __launch_bounds__(256) void gather128_kernel(
    const float* __restrict__ hs, const int* __restrict__ rs,
    const int* __restrict__ csrc, const float* __restrict__ dinv,
    const float* __restrict__ b, float* __restrict__ out, int N)
{
    int node = (blockIdx.x * blockDim.x + threadIdx.x) >> 5;
    int lane = threadIdx.x & 31;
    if (node >= N) return;
    int beg = rs[node], end = rs[node + 1];
    const float4* h4 = reinterpret_cast<const float4*>(hs);

    float4 a0 = h4[(size_t)node * 32 + lane];   // self (already dinv-scaled)
    float4 a1 = make_float4(0.f, 0.f, 0.f, 0.f);
    int j = beg;
    for (; j + 1 < end; j += 2) {
        int s0 = csrc[j], s1 = csrc[j + 1];
        float4 v0 = h4[(size_t)s0 * 32 + lane];
        float4 v1 = h4[(size_t)s1 * 32 + lane];
        a0.x += v0.x; a0.y += v0.y; a0.z += v0.z; a0.w += v0.w;
        a1.x += v1.x; a1.y += v1.y; a1.z += v1.z; a1.w += v1.w;
    }
    if (j < end) {
        int s0 = csrc[j];
        float4 v0 = h4[(size_t)s0 * 32 + lane];
        a0.x += v0.x; a0.y += v0.y; a0.z += v0.z; a0.w += v0.w;
    }
    float dd = dinv[node];
    float4 bv = reinterpret_cast<const float4*>(b)[lane];
    float4 r;
    r.x = fmaf(dd, a0.x + a1.x, bv.x);
    r.y = fmaf(dd, a0.y + a1.y, bv.y);
    r.z = fmaf(dd, a0.z + a1.z, bv.z);
    r.w = fmaf(dd, a0.w + a1.w, bv.w);
    if (RELU) {
        r.x = fmaxf(r.x, 0.f); r.y = fmaxf(r.y, 0.f);
        r.z = fmaxf(r.z, 0.f); r.w = fmaxf(r.w, 0.f);
    }
    reinterpret_cast<float4*>(out)[(size_t)node * 32 + lane] = r;
}

// ---------------- CSR gather, 64 feats: one warp per node (float2/lane) ------
__global__ __launch_bounds__(256) void gather64_kernel(
    const float* __restrict__ hs, const int* __restrict__ rs,
    const int* __restrict__ csrc, const float* __restrict__ dinv,
    const float* __restrict__ b, float* __restrict__ out, int N)
{
    int node = (blockIdx.x * blockDim.x + threadIdx.x) >> 5;
    int lane = threadIdx.x & 31;
    if (node >= N) return;
    int beg = rs[node], end = rs[node + 1];
    const float2* h2 = reinterpret_cast<const float2*>(hs);

    float2 a0 = h2[(size_t)node * 32 + lane];
    float2 a1 = make_float2(0.f, 0.f);
    int j = beg;
    for (; j + 1 < end; j += 2) {
        int s0 = csrc[j], s1 = csrc[j + 1];
        float2 v0 = h2[(size_t)s0 * 32 + lane];
        float2 v1 = h2[(size_t)s1 * 32 + lane];
        a0.x += v0.x; a0.y += v0.y;
        a1.x += v1.x; a1.y += v1.y;
    }
    if (j < end) {
        int s0 = csrc[j];
        float2 v0 = h2[(size_t)s0 * 32 + lane];
        a0.x += v0.x; a0.y += v0.y;
    }
    float dd = dinv[node];
    float2 bv = reinterpret_cast<const float2*>(b)[lane];
    float2 r;
    r.x = fmaf(dd, a0.x + a1.x, bv.x);
    r.y = fmaf(dd, a0.y + a1.y, bv.y);
    reinterpret_cast<float2*>(out)[(size_t)node * 32 + lane] = r;
}

// -----------------------------------------------------------------------------
extern "C" void kernel_launch(void* const* d_in, const int* in_sizes, int n_in,
                              void* d_out, int out_size)
{
    const float* x  = (const float*)d_in[0];
    const int*   ei = (const int*)  d_in[1];
    const float* W1 = (const float*)d_in[2];
    const float* b1 = (const float*)d_in[3];
    const float* W2 = (const float*)d_in[4];
    const float* b2 = (const float*)d_in[5];
    float* out = (float*)d_out;

    const int hid1 = in_sizes[3];            // 128
    const int feat = in_sizes[2] / hid1;     // 128
    const int N    = in_sizes[0] / feat;     // 50000
    const int E    = in_sizes[1] / 2;        // 800000
    const int* src = ei;
    const int* dst = ei + E;

    void *p_h1, *p_a1, *p_h2, *p_deg, *p_dinv, *p_rs, *p_cur, *p_csrc, *p_bsum;
    cudaGetSymbolAddress(&p_h1,   g_h1);
    cudaGetSymbolAddress(&p_a1,   g_a1);
    cudaGetSymbolAddress(&p_h2,   g_h2);
    cudaGetSymbolAddress(&p_deg,  g_deg);
    cudaGetSymbolAddress(&p_dinv, g_dinv);
    cudaGetSymbolAddress(&p_rs,   g_rowstart);
    cudaGetSymbolAddress(&p_cur,  g_cursor);
    cudaGetSymbolAddress(&p_csrc, g_csrc);
    cudaGetSymbolAddress(&p_bsum, g_bsum);
    float* h1   = (float*)p_h1;
    float* a1   = (float*)p_a1;
    float* h2   = (float*)p_h2;
    int*   deg  = (int*)  p_deg;
    float* dinv = (float*)p_dinv;
    int*   rs   = (int*)  p_rs;
    int*   cur  = (int*)  p_cur;
    int*   csrc = (int*)  p_csrc;
    int*   bsum = (int*)  p_bsum;

    static bool attr_done = false;
    if (!attr_done) {
        cudaFuncSetAttribute(gemm_f32x2_kernel<HID1>,
                             cudaFuncAttributeMaxDynamicSharedMemorySize, GEMM_SMEM);
        cudaFuncSetAttribute(gemm_f32x2_kernel<HID2>,
                             cudaFuncAttributeMaxDynamicSharedMemorySize, GEMM_SMEM);
        attr_done = true;
    }

    const int T = 256;
    const int nscan = (N + SCAN_B - 1) / SCAN_B;    // 49 blocks

    // 1) degree + dinv + CSR build (multi-block scan)
    zero_i_kernel<<<(N + T - 1) / T, T>>>(deg, N);
    count_deg_kernel<<<(E + T - 1) / T, T>>>(dst, deg, E);
    dinv_kernel<<<(N + T - 1) / T, T>>>(deg, dinv, N);
    scan_blocks_kernel<<<nscan, SCAN_B>>>(deg, rs, bsum, N);
    scan_bsums_kernel<<<1, 64>>>(bsum, nscan);
    scan_add_kernel<<<nscan, SCAN_B>>>(rs, cur, bsum, N, nscan);
    fill_csr_kernel<<<(E + T - 1) / T, T>>>(src, dst, cur, csrc, E);

    const int gx = (N + 127) / 128;
    const int gwarp = (N * 32 + T - 1) / T;   // blocks for one-warp-per-node

    // 2) layer 1: h1 = dinv * (x @ W1)
    {
        dim3 grid(gx, HID1 / 64);
        gemm_f32x2_kernel<HID1><<<grid, 256, GEMM_SMEM>>>(x, W1, dinv, h1, N);
    }
    // 3) gather layer 1: a1 = relu(dinv * (sum nbr + self) + b1)
    gather128_kernel<true><<<gwarp, T>>>(h1, rs, csrc, dinv, b1, a1, N);

    // 4) layer 2: h2 = dinv * (a1 @ W2)
    {
        dim3 grid(gx, HID2 / 64);
        gemm_f32x2_kernel<HID2><<<grid, 256, GEMM_SMEM>>>(a1, W2, dinv, h2, N);
    }
    // 5) gather layer 2 into out (no relu)
    gather64_kernel<<<gwarp, T>>>(h2, rs, csrc, dinv, b2, out, N);
}

// round 6
// speedup vs baseline: 2.4379x; 1.3300x over previous
#include <cuda_runtime.h>
#include <cuda_bf16.h>
#include <cstdint>

// Problem constants (GCL_GCN: N=50000, E=800000, FEAT=128, HID1=128, HID2=64)
#define N_MAX   50000
#define E_MAX   800000
#define HID1    128
#define HID2    64
#define SCAN_B  1024
#define SCAN_NBLOCKS ((N_MAX + SCAN_B - 1) / SCAN_B + 1)

// ---------------- scratch (static device globals; no allocation) -------------
__device__ float g_h1  [(size_t)N_MAX * HID1];   // X @ W1 (unscaled)
__device__ float g_a1  [(size_t)N_MAX * HID1];   // relu(aggregated layer1)
__device__ float g_h2  [(size_t)N_MAX * HID2];   // a1 @ W2 (unscaled)
__device__ int   g_deg [N_MAX];
__device__ float g_dinv[N_MAX];
__device__ int   g_rowstart[N_MAX + 1];
__device__ int   g_cursor  [N_MAX];
__device__ int   g_csrc    [E_MAX];              // edges sorted by dst -> src ids
__device__ int   g_bsum    [SCAN_NBLOCKS + 1];   // per-block scan sums

// ---------------- helpers -----------------------------------------------------
__device__ __forceinline__ uint32_t cvt_tf32(float f) {
    uint32_t r;
    asm("cvt.rna.tf32.f32 %0, %1;" : "=r"(r) : "f"(f));
    return r;
}
__device__ __forceinline__ void mma_tf32(
    float* c, const uint32_t* a, uint32_t b0, uint32_t b1)
{
    asm volatile(
        "mma.sync.aligned.m16n8k8.row.col.f32.tf32.tf32.f32 "
        "{%0,%1,%2,%3}, {%4,%5,%6,%7}, {%8,%9}, {%0,%1,%2,%3};"
        : "+f"(c[0]), "+f"(c[1]), "+f"(c[2]), "+f"(c[3])
        : "r"(a[0]), "r"(a[1]), "r"(a[2]), "r"(a[3]), "r"(b0), "r"(b1));
}

// ---------------- degree / dinv ----------------------------------------------
__global__ void zero_i_kernel(int* __restrict__ p, int n) {
    int i = blockIdx.x * blockDim.x + threadIdx.x;
    if (i < n) p[i] = 0;
}
__global__ void count_deg_kernel(const int* __restrict__ dst, int* __restrict__ deg, int E) {
    int e = blockIdx.x * blockDim.x + threadIdx.x;
    if (e < E) atomicAdd(&deg[dst[e]], 1);
}
__global__ void dinv_kernel(const int* __restrict__ deg, float* __restrict__ dinv, int N) {
    int i = blockIdx.x * blockDim.x + threadIdx.x;
    if (i < N) dinv[i] = rsqrtf((float)(deg[i] + 1));  // +1 self-loop
}

// ---------------- multi-block exclusive scan ----------------------------------
__global__ __launch_bounds__(SCAN_B) void scan_blocks_kernel(
    const int* __restrict__ deg, int* __restrict__ row_start,
    int* __restrict__ bsum, int N)
{
    __shared__ int warp_sums[32];
    const int lane = threadIdx.x & 31;
    const int wid  = threadIdx.x >> 5;
    int i = blockIdx.x * SCAN_B + threadIdx.x;
    int v = (i < N) ? deg[i] : 0;
    int x = v;
    #pragma unroll
    for (int o = 1; o < 32; o <<= 1) {
        int t = __shfl_up_sync(0xffffffffu, x, o);
        if (lane >= o) x += t;
    }
    if (lane == 31) warp_sums[wid] = x;
    __syncthreads();
    if (wid == 0) {
        int ws = warp_sums[lane];
        #pragma unroll
        for (int o = 1; o < 32; o <<= 1) {
            int t = __shfl_up_sync(0xffffffffu, ws, o);
            if (lane >= o) ws += t;
        }
        warp_sums[lane] = ws;
    }
    __syncthreads();
    int excl = x - v + (wid > 0 ? warp_sums[wid - 1] : 0);
    if (i < N) row_start[i] = excl;
    if (threadIdx.x == SCAN_B - 1) bsum[blockIdx.x] = excl + v;
}

__global__ __launch_bounds__(64) void scan_bsums_kernel(int* __restrict__ bsum, int nblocks) {
    const int lane = threadIdx.x & 31;
    const int wid  = threadIdx.x >> 5;
    __shared__ int wsum[2];
    int v = (threadIdx.x < nblocks) ? bsum[threadIdx.x] : 0;
    int x = v;
    #pragma unroll
    for (int o = 1; o < 32; o <<= 1) {
        int t = __shfl_up_sync(0xffffffffu, x, o);
        if (lane >= o) x += t;
    }
    if (lane == 31) wsum[wid] = x;
    __syncthreads();
    int excl = x - v + (wid > 0 ? wsum[0] : 0);
    if (threadIdx.x < nblocks) bsum[threadIdx.x] = excl;
    if (threadIdx.x == nblocks - 1) bsum[nblocks] = excl + v;  // grand total
}

__global__ __launch_bounds__(SCAN_B) void scan_add_kernel(
    int* __restrict__ row_start, int* __restrict__ cursor,
    const int* __restrict__ bsum, int N, int nblocks)
{
    int i = blockIdx.x * SCAN_B + threadIdx.x;
    if (i < N) {
        int r = row_start[i] + bsum[blockIdx.x];
        row_start[i] = r;
        cursor[i]    = r;
    }
    if (i == 0) row_start[N] = bsum[nblocks];
}

// ---------------- fill CSR: csrc sorted by dst --------------------------------
__global__ void fill_csr_kernel(
    const int* __restrict__ src, const int* __restrict__ dst,
    int* __restrict__ cursor, int* __restrict__ csrc, int E)
{
    int e = blockIdx.x * blockDim.x + threadIdx.x;
    if (e < E) {
        int pos = atomicAdd(&cursor[dst[e]], 1);
        csrc[pos] = src[e];
    }
}

// ---------------- tf32 HMMA GEMM: H = X[N,128] @ W[128,COUT] -------------------
// CTA: 256 thr (8 warps), tile 128 rows x COUT cols. Warp tile 32 x COUT/2
// (warp grid 4x2). mma.sync m16n8k8 tf32. SMEM strides padded (+4 words) so
// both A- and B-fragment LDS are bank-conflict-free (bank = 4*g + t).
#define HG_SMEM(COUT) ((128 * 132 + 128 * ((COUT) + 4)) * 4)

template<int COUT>
__global__ __launch_bounds__(256) void hmma_gemm_kernel(
    const float* __restrict__ X, const float* __restrict__ W,
    float* __restrict__ H, int N)
{
    constexpr int XS = 132;             // X row stride (words)
    constexpr int WS = COUT + 4;        // W row stride (words)
    constexpr int NT = COUT / 16;       // n-tiles per warp (warp cols = COUT/2)
    extern __shared__ uint32_t smu[];
    uint32_t* Xs = smu;                 // [128][XS]
    uint32_t* Ws = smu + 128 * XS;      // [128][WS]

    const int tid   = threadIdx.x;
    const int wid   = tid >> 5;
    const int lane  = tid & 31;
    const int g     = lane >> 2;        // fragment group (0..7)
    const int t     = lane & 3;         // thread-in-group (0..3)
    const int rbase = blockIdx.x * 128;

    // ---- stage X tile [128 r][128 k], fp32 -> tf32 ----
    const float4* Xg4 = reinterpret_cast<const float4*>(X);
    #pragma unroll
    for (int it = 0; it < 16; ++it) {
        int i  = tid + it * 256;
        int r  = i >> 5, k4 = i & 31;
        int gr = rbase + r;
        float4 v = (gr < N) ? Xg4[(size_t)gr * 32 + k4]
                            : make_float4(0.f, 0.f, 0.f, 0.f);
        uint4 u = make_uint4(cvt_tf32(v.x), cvt_tf32(v.y),
                             cvt_tf32(v.z), cvt_tf32(v.w));
        *reinterpret_cast<uint4*>(&Xs[r * XS + k4 * 4]) = u;
    }
    // ---- stage W [128 k][COUT n], fp32 -> tf32 ----
    const float4* Wg4 = reinterpret_cast<const float4*>(W);
    constexpr int W4 = COUT / 4;
    #pragma unroll
    for (int it = 0; it < (128 * W4) / 256; ++it) {
        int i = tid + it * 256;
        int k = i / W4, n4 = i % W4;
        float4 v = Wg4[i];
        uint4 u = make_uint4(cvt_tf32(v.x), cvt_tf32(v.y),
                             cvt_tf32(v.z), cvt_tf32(v.w));
        *reinterpret_cast<uint4*>(&Ws[k * WS + n4 * 4]) = u;
    }
    __syncthreads();

    // ---- main loop: 16 k-steps of k=8 ----
    const int wr = (wid >> 1) * 32;             // warp row base
    const int wc = (wid & 1) * (COUT / 2);      // warp col base
    float c[2][NT][4];
    #pragma unroll
    for (int rb = 0; rb < 2; ++rb)
        #pragma unroll
        for (int nt = 0; nt < NT; ++nt)
            #pragma unroll
            for (int j = 0; j < 4; ++j) c[rb][nt][j] = 0.f;

    #pragma unroll
    for (int ks = 0; ks < 16; ++ks) {
        const int k0 = ks * 8;
        uint32_t a[2][4];
        #pragma unroll
        for (int rb = 0; rb < 2; ++rb) {
            const uint32_t* xb = &Xs[(wr + rb * 16 + g) * XS + k0 + t];
            a[rb][0] = xb[0];
            a[rb][2] = xb[4];
            a[rb][1] = xb[8 * XS];
            a[rb][3] = xb[8 * XS + 4];
        }
        #pragma unroll
        for (int nt = 0; nt < NT; ++nt) {
            uint32_t b0 = Ws[(k0 + t) * WS + wc + nt * 8 + g];
            uint32_t b1 = Ws[(k0 + t + 4) * WS + wc + nt * 8 + g];
            mma_tf32(c[0][nt], a[0], b0, b1);
            mma_tf32(c[1][nt], a[1], b0, b1);
        }
    }

    // ---- epilogue: direct stores (32B-sector aligned float2 per c-pair) ----
    #pragma unroll
    for (int rb = 0; rb < 2; ++rb) {
        int r0 = rbase + wr + rb * 16 + g;
        #pragma unroll
        for (int nt = 0; nt < NT; ++nt) {
            int col = wc + nt * 8 + 2 * t;
            if (r0 < N)
                *reinterpret_cast<float2*>(&H[(size_t)r0 * COUT + col]) =
                    make_float2(c[rb][nt][0], c[rb][nt][1]);
            if (r0 + 8 < N)
                *reinterpret_cast<float2*>(&H[(size_t)(r0 + 8) * COUT + col]) =
                    make_float2(c[rb][nt][2], c[rb][nt][3]);
        }
    }
}

// ---------------- CSR gather, 128 feats: one warp per node -------------------
// sum = dinv_d * h[d] + sum_s dinv_s * h[s];  out = act(dinv_d * sum + b)
template<bool RELU>
__global__ __launch_bounds__(256) void gather128_kernel(
    const float* __restrict__ hs, const int* __restrict__ rs,
    const int* __restrict__ csrc, const float* __restrict__ dinv,
    const float* __restrict__ b, float* __restrict__ out, int N)
{
    int node = (blockIdx.x * blockDim.x + threadIdx.x) >> 5;
    int lane = threadIdx.x & 31;
    if (node >= N) return;
    int beg = rs[node], end = rs[node + 1];
    const float4* h4 = reinterpret_cast<const float4*>(hs);
    float dd = dinv[node];

    float4 sv = h4[(size_t)node * 32 + lane];
    float4 a0 = make_float4(sv.x * dd, sv.y * dd, sv.z * dd, sv.w * dd);
    float4 a1 = make_float4(0.f, 0.f, 0.f, 0.f);
    int j = beg;
    for (; j + 1 < end; j += 2) {
        int s0 = csrc[j], s1 = csrc[j + 1];
        float n0 = dinv[s0], n1 = dinv[s1];
        float4 v0 = h4[(size_t)s0 * 32 + lane];
        float4 v1 = h4[(size_t)s1 * 32 + lane];
        a0.x = fmaf(v0.x, n0, a0.x); a0.y = fmaf(v0.y, n0, a0.y);
        a0.z = fmaf(v0.z, n0, a0.z); a0.w = fmaf(v0.w, n0, a0.w);
        a1.x = fmaf(v1.x, n1, a1.x); a1.y = fmaf(v1.y, n1, a1.y);
        a1.z = fmaf(v1.z, n1, a1.z); a1.w = fmaf(v1.w, n1, a1.w);
    }
    if (j < end) {
        int s0 = csrc[j];
        float n0 = dinv[s0];
        float4 v0 = h4[(size_t)s0 * 32 + lane];
        a0.x = fmaf(v0.x, n0, a0.x); a0.y = fmaf(v0.y, n0, a0.y);
        a0.z = fmaf(v0.z, n0, a0.z); a0.w = fmaf(v0.w, n0, a0.w);
    }
    float4 bv = reinterpret_cast<const float4*>(b)[lane];
    float4 r;
    r.x = fmaf(dd, a0.x + a1.x, bv.x);
    r.y = fmaf(dd, a0.y + a1.y, bv.y);
    r.z = fmaf(dd, a0.z + a1.z, bv.z);
    r.w = fmaf(dd, a0.w + a1.w, bv.w);
    if (RELU) {
        r.x = fmaxf(r.x, 0.f); r.y = fmaxf(r.y, 0.f);
        r.z = fmaxf(r.z, 0.f); r.w = fmaxf(r.w, 0.f);
    }
    reinterpret_cast<float4*>(out)[(size_t)node * 32 + lane] = r;
}

// ---------------- CSR gather, 64 feats: one warp per node --------------------
__global__ __launch_bounds__(256) void gather64_kernel(
    const float* __restrict__ hs, const int* __restrict__ rs,
    const int* __restrict__ csrc, const float* __restrict__ dinv,
    const float* __restrict__ b, float* __restrict__ out, int N)
{
    int node = (blockIdx.x * blockDim.x + threadIdx.x) >> 5;
    int lane = threadIdx.x & 31;
    if (node >= N) return;
    int beg = rs[node], end = rs[node + 1];
    const float2* h2 = reinterpret_cast<const float2*>(hs);
    float dd = dinv[node];

    float2 sv = h2[(size_t)node * 32 + lane];
    float2 a0 = make_float2(sv.x * dd, sv.y * dd);
    float2 a1 = make_float2(0.f, 0.f);
    int j = beg;
    for (; j + 1 < end; j += 2) {
        int s0 = csrc[j], s1 = csrc[j + 1];
        float n0 = dinv[s0], n1 = dinv[s1];
        float2 v0 = h2[(size_t)s0 * 32 + lane];
        float2 v1 = h2[(size_t)s1 * 32 + lane];
        a0.x = fmaf(v0.x, n0, a0.x); a0.y = fmaf(v0.y, n0, a0.y);
        a1.x = fmaf(v1.x, n1, a1.x); a1.y = fmaf(v1.y, n1, a1.y);
    }
    if (j < end) {
        int s0 = csrc[j];
        float n0 = dinv[s0];
        float2 v0 = h2[(size_t)s0 * 32 + lane];
        a0.x = fmaf(v0.x, n0, a0.x); a0.y = fmaf(v0.y, n0, a0.y);
    }
    float2 bv = reinterpret_cast<const float2*>(b)[lane];
    float2 r;
    r.x = fmaf(dd, a0.x + a1.x, bv.x);
    r.y = fmaf(dd, a0.y + a1.y, bv.y);
    reinterpret_cast<float2*>(out)[(size_t)node * 32 + lane] = r;
}

// -----------------------------------------------------------------------------
extern "C" void kernel_launch(void* const* d_in, const int* in_sizes, int n_in,
                              void* d_out, int out_size)
{
    const float* x  = (const float*)d_in[0];
    const int*   ei = (const int*)  d_in[1];
    const float* W1 = (const float*)d_in[2];
    const float* b1 = (const float*)d_in[3];
    const float* W2 = (const float*)d_in[4];
    const float* b2 = (const float*)d_in[5];
    float* out = (float*)d_out;

    const int hid1 = in_sizes[3];            // 128
    const int feat = in_sizes[2] / hid1;     // 128
    const int N    = in_sizes[0] / feat;     // 50000
    const int E    = in_sizes[1] / 2;        // 800000
    const int* src = ei;
    const int* dst = ei + E;

    void *p_h1, *p_a1, *p_h2, *p_deg, *p_dinv, *p_rs, *p_cur, *p_csrc, *p_bsum;
    cudaGetSymbolAddress(&p_h1,   g_h1);
    cudaGetSymbolAddress(&p_a1,   g_a1);
    cudaGetSymbolAddress(&p_h2,   g_h2);
    cudaGetSymbolAddress(&p_deg,  g_deg);
    cudaGetSymbolAddress(&p_dinv, g_dinv);
    cudaGetSymbolAddress(&p_rs,   g_rowstart);
    cudaGetSymbolAddress(&p_cur,  g_cursor);
    cudaGetSymbolAddress(&p_csrc, g_csrc);
    cudaGetSymbolAddress(&p_bsum, g_bsum);
    float* h1   = (float*)p_h1;
    float* a1   = (float*)p_a1;
    float* h2   = (float*)p_h2;
    int*   deg  = (int*)  p_deg;
    float* dinv = (float*)p_dinv;
    int*   rs   = (int*)  p_rs;
    int*   cur  = (int*)  p_cur;
    int*   csrc = (int*)  p_csrc;
    int*   bsum = (int*)  p_bsum;

    // one-time setup: smem attrs + side stream/events for the CSR fork
    static cudaStream_t s_csr = nullptr;
    static cudaEvent_t  ev_root = nullptr, ev_csr = nullptr;
    if (s_csr == nullptr) {
        cudaFuncSetAttribute(hmma_gemm_kernel<HID1>,
                             cudaFuncAttributeMaxDynamicSharedMemorySize, HG_SMEM(HID1));
        cudaFuncSetAttribute(hmma_gemm_kernel<HID2>,
                             cudaFuncAttributeMaxDynamicSharedMemorySize, HG_SMEM(HID2));
        cudaStreamCreateWithFlags(&s_csr, cudaStreamNonBlocking);
        cudaEventCreateWithFlags(&ev_root, cudaEventDisableTiming);
        cudaEventCreateWithFlags(&ev_csr,  cudaEventDisableTiming);
    }

    const int T = 256;
    const int nscan = (N + SCAN_B - 1) / SCAN_B;    // 49 blocks
    const int gx    = (N + 127) / 128;
    const int gwarp = (N * 32 + T - 1) / T;

    // ---- fork: CSR/degree chain on side stream, GEMM1 on main stream ----
    cudaEventRecord(ev_root, 0);
    cudaStreamWaitEvent(s_csr, ev_root, 0);

    zero_i_kernel   <<<(N + T - 1) / T, T, 0, s_csr>>>(deg, N);
    count_deg_kernel<<<(E + T - 1) / T, T, 0, s_csr>>>(dst, deg, E);
    dinv_kernel     <<<(N + T - 1) / T, T, 0, s_csr>>>(deg, dinv, N);
    scan_blocks_kernel<<<nscan, SCAN_B, 0, s_csr>>>(deg, rs, bsum, N);
    scan_bsums_kernel <<<1, 64, 0, s_csr>>>(bsum, nscan);
    scan_add_kernel   <<<nscan, SCAN_B, 0, s_csr>>>(rs, cur, bsum, N, nscan);
    fill_csr_kernel   <<<(E + T - 1) / T, T, 0, s_csr>>>(src, dst, cur, csrc, E);
    cudaEventRecord(ev_csr, s_csr);

    // layer 1 GEMM (independent of degree chain): h1 = x @ W1
    hmma_gemm_kernel<HID1><<<gx, 256, HG_SMEM(HID1)>>>(x, W1, h1, N);

    // join: gathers need CSR + dinv
    cudaStreamWaitEvent(0, ev_csr, 0);

    // gather layer 1: a1 = relu(dinv_d * (dinv_d*h1[d] + sum dinv_s*h1[s]) + b1)
    gather128_kernel<true><<<gwarp, T>>>(h1, rs, csrc, dinv, b1, a1, N);

    // layer 2 GEMM: h2 = a1 @ W2
    hmma_gemm_kernel<HID2><<<gx, 256, HG_SMEM(HID2)>>>(a1, W2, h2, N);

    // gather layer 2 into out (no relu)
    gather64_kernel<<<gwarp, T>>>(h2, rs, csrc, dinv, b2, out, N);
}